// round 3
// baseline (speedup 1.0000x reference)
#include <cuda_runtime.h>
#include <math.h>

// Problem constants (fixed by setup_inputs)
#define NN   50000
#define EE   800000
#define EP   850000      // EE + NN self loops
#define FIN  128
#define H1   4
#define HID  64
#define HC   256         // H1*HID
#define NC   10
#define NEG_SLOPE 0.2f
#define NEGINF_KEY 0x007FFFFFu   // fkey(-inf)

// ---------------- scratch (device globals; no runtime allocation) ----------
static __device__ __align__(16) float        g_h1[(size_t)NN * HC];     // 51.2 MB
static __device__ __align__(16) float        g_as1[NN * H1];
static __device__ __align__(16) float        g_ad1[NN * H1];
static __device__ __align__(16) unsigned int g_max1[NN * H1];
static __device__ __align__(16) float        g_sum1[NN * H1];
static __device__ __align__(16) float        g_e1[(size_t)EP * H1];     // 13.6 MB
static __device__ __align__(16) float        g_agg1[(size_t)NN * HC];   // 51.2 MB
static __device__ __align__(16) float        g_h2[NN * NC];
static __device__ __align__(16) float        g_as2[NN];
static __device__ __align__(16) float        g_ad2[NN];
static __device__ __align__(16) unsigned int g_max2[NN];
static __device__ __align__(16) float        g_sum2[NN];
static __device__ __align__(16) float        g_e2[EP];
static __device__ __align__(16) float        g_agg2[NN * NC];

// ---------------- helpers ----------------
__device__ __forceinline__ unsigned int fkey(float f) {
    unsigned int u = __float_as_uint(f);
    return (u & 0x80000000u) ? ~u : (u | 0x80000000u);
}
__device__ __forceinline__ float funkey(unsigned int k) {
    unsigned int u = (k & 0x80000000u) ? (k & 0x7FFFFFFFu) : ~k;
    return __uint_as_float(u);
}
__device__ __forceinline__ float lrelu(float x) {
    return (x > 0.f) ? x : NEG_SLOPE * x;
}
// defensive clamp: if index dtype assumption is ever wrong we get a finite
// wrong answer (rel_err signal) instead of an illegal access
__device__ __forceinline__ int clampN(int v) {
    return v < 0 ? 0 : (v >= NN ? NN - 1 : v);
}

// ---------------- GEMM1: h1 = x @ W1  [NN,128]x[128,256] ----------------
#define BM 64
#define BN 64
#define BK 16

__global__ __launch_bounds__(256) void k_gemm1(const float* __restrict__ X,
                                               const float* __restrict__ W) {
    __shared__ float As[BK][BM + 4];
    __shared__ float Bs[BK][BN];
    const int m0 = blockIdx.y * BM;
    const int n0 = blockIdx.x * BN;
    const int t  = threadIdx.x;
    const int ty = t >> 4;      // 0..15
    const int tx = t & 15;      // 0..15
    const int lr = t >> 2;      // 0..63 row (A tile)
    const int lv = t & 3;       // 0..3  float4-in-row (k dim)
    const int bkr = t >> 4;     // 0..15 k-row (B tile)
    const int bv  = t & 15;     // 0..15 float4-in-row (n dim)

    float acc[4][4];
#pragma unroll
    for (int i = 0; i < 4; i++)
#pragma unroll
        for (int j = 0; j < 4; j++) acc[i][j] = 0.f;

    for (int k0 = 0; k0 < FIN; k0 += BK) {
        float4 a4 = make_float4(0.f, 0.f, 0.f, 0.f);
        const int gr = m0 + lr;
        if (gr < NN)
            a4 = *(const float4*)(X + (size_t)gr * FIN + k0 + lv * 4);
        As[lv * 4 + 0][lr] = a4.x;
        As[lv * 4 + 1][lr] = a4.y;
        As[lv * 4 + 2][lr] = a4.z;
        As[lv * 4 + 3][lr] = a4.w;

        float4 b4 = *(const float4*)(W + (size_t)(k0 + bkr) * HC + n0 + bv * 4);
        *(float4*)&Bs[bkr][bv * 4] = b4;
        __syncthreads();

#pragma unroll
        for (int k = 0; k < BK; k++) {
            float a[4], b[4];
#pragma unroll
            for (int i = 0; i < 4; i++) a[i] = As[k][ty * 4 + i];
#pragma unroll
            for (int j = 0; j < 4; j++) b[j] = Bs[k][tx * 4 + j];
#pragma unroll
            for (int i = 0; i < 4; i++)
#pragma unroll
                for (int j = 0; j < 4; j++) acc[i][j] += a[i] * b[j];
        }
        __syncthreads();
    }
#pragma unroll
    for (int i = 0; i < 4; i++) {
        const int gr = m0 + ty * 4 + i;
        if (gr < NN) {
            float4 o = make_float4(acc[i][0], acc[i][1], acc[i][2], acc[i][3]);
            *(float4*)(g_h1 + (size_t)gr * HC + n0 + tx * 4) = o;
        }
    }
}

// ---------------- a_src1/a_dst1 + init max/sum ----------------
__global__ __launch_bounds__(256) void k_asad1(const float* __restrict__ att_src,
                                               const float* __restrict__ att_dst) {
    const int idx = blockIdx.x * blockDim.x + threadIdx.x;
    if (idx >= NN * H1) return;
    const int n = idx >> 2;
    const int h = idx & 3;
    const float* hp  = g_h1 + (size_t)n * HC + h * HID;
    const float* asp = att_src + h * HID;
    const float* adp = att_dst + h * HID;
    float ss = 0.f, sd = 0.f;
#pragma unroll
    for (int c4 = 0; c4 < HID / 4; c4++) {
        float4 v = *(const float4*)(hp + c4 * 4);
        float4 a = *(const float4*)(asp + c4 * 4);
        float4 d = *(const float4*)(adp + c4 * 4);
        ss += v.x * a.x + v.y * a.y + v.z * a.z + v.w * a.w;
        sd += v.x * d.x + v.y * d.y + v.z * d.z + v.w * d.w;
    }
    g_as1[idx]  = ss;
    g_ad1[idx]  = sd;
    g_max1[idx] = NEGINF_KEY;
    g_sum1[idx] = 0.f;
}

// ---------------- zero agg1 ----------------
__global__ __launch_bounds__(256) void k_zero1() {
    const int idx = blockIdx.x * blockDim.x + threadIdx.x;
    if (idx < NN * HC / 4)
        ((float4*)g_agg1)[idx] = make_float4(0.f, 0.f, 0.f, 0.f);
}

// ---------------- layer1 edge pass B: logits + segment max ----------------
__global__ __launch_bounds__(256) void k_edge1_logit(const int* __restrict__ esrc,
                                                     const int* __restrict__ edst) {
    const int e = blockIdx.x * blockDim.x + threadIdx.x;
    if (e >= EP) return;
    int s, d;
    if (e < EE) { s = clampN(esrc[e]); d = clampN(edst[e]); }
    else        { s = d = e - EE; }
    float4 as = *(const float4*)(g_as1 + s * 4);
    float4 ad = *(const float4*)(g_ad1 + d * 4);
    float4 l;
    l.x = lrelu(as.x + ad.x);
    l.y = lrelu(as.y + ad.y);
    l.z = lrelu(as.z + ad.z);
    l.w = lrelu(as.w + ad.w);
    *(float4*)(g_e1 + (size_t)e * 4) = l;
    atomicMax(&g_max1[d * 4 + 0], fkey(l.x));
    atomicMax(&g_max1[d * 4 + 1], fkey(l.y));
    atomicMax(&g_max1[d * 4 + 2], fkey(l.z));
    atomicMax(&g_max1[d * 4 + 3], fkey(l.w));
}

// ---------------- layer1 edge pass C: exp + segment sum ----------------
__global__ __launch_bounds__(256) void k_edge1_exp(const int* __restrict__ edst) {
    const int e = blockIdx.x * blockDim.x + threadIdx.x;
    if (e >= EP) return;
    const int d = (e < EE) ? clampN(edst[e]) : (e - EE);
    float4 l = *(const float4*)(g_e1 + (size_t)e * 4);
    uint4  mk = *(const uint4*)(g_max1 + d * 4);
    float4 ex;
    ex.x = expf(l.x - funkey(mk.x));
    ex.y = expf(l.y - funkey(mk.y));
    ex.z = expf(l.z - funkey(mk.z));
    ex.w = expf(l.w - funkey(mk.w));
    *(float4*)(g_e1 + (size_t)e * 4) = ex;
    atomicAdd(&g_sum1[d * 4 + 0], ex.x);
    atomicAdd(&g_sum1[d * 4 + 1], ex.y);
    atomicAdd(&g_sum1[d * 4 + 2], ex.z);
    atomicAdd(&g_sum1[d * 4 + 3], ex.w);
}

// ---------------- layer1 aggregation: warp per edge, float4 atomics --------
__global__ __launch_bounds__(256) void k_edge1_agg(const int* __restrict__ esrc,
                                                   const int* __restrict__ edst) {
    const int w    = (blockIdx.x * blockDim.x + threadIdx.x) >> 5;
    const int lane = threadIdx.x & 31;
    if (w >= EP) return;
    int s, d;
    if (w < EE) { s = clampN(esrc[w]); d = clampN(edst[w]); }
    else        { s = d = w - EE; }
    float4 e4 = *(const float4*)(g_e1 + (size_t)w * 4);
    float4 s4 = *(const float4*)(g_sum1 + d * 4);
    float4 al = make_float4(e4.x / s4.x, e4.y / s4.y, e4.z / s4.z, e4.w / s4.w);
    const float a0 = (lane < 16) ? al.x : al.y;   // cols 0..127  -> heads 0,1
    const float a1 = (lane < 16) ? al.z : al.w;   // cols 128..255 -> heads 2,3
    const float* hs = g_h1   + (size_t)s * HC;
    float*       od = g_agg1 + (size_t)d * HC;
    const int c0 = lane * 4;
    float4 v0 = *(const float4*)(hs + c0);
    atomicAdd((float4*)(od + c0),
              make_float4(v0.x * a0, v0.y * a0, v0.z * a0, v0.w * a0));
    float4 v1 = *(const float4*)(hs + c0 + 128);
    atomicAdd((float4*)(od + c0 + 128),
              make_float4(v1.x * a1, v1.y * a1, v1.z * a1, v1.w * a1));
}

// ---- fused: bias+ELU, GEMM2 (256->10), a_src2/a_dst2, init layer2 state ---
__global__ __launch_bounds__(256) void k_node2(const float* __restrict__ b1,
                                               const float* __restrict__ W2,
                                               const float* __restrict__ att_src2,
                                               const float* __restrict__ att_dst2) {
    const int n    = (blockIdx.x * blockDim.x + threadIdx.x) >> 5;
    const int lane = threadIdx.x & 31;
    if (n >= NN) return;
    float v[8];
#pragma unroll
    for (int j = 0; j < 8; j++) {
        const int col = lane + 32 * j;
        float x = g_agg1[(size_t)n * HC + col] + b1[col];
        v[j] = (x > 0.f) ? x : expm1f(x);
    }
    float h2v[NC];
#pragma unroll
    for (int k = 0; k < NC; k++) {
        float p = 0.f;
#pragma unroll
        for (int j = 0; j < 8; j++)
            p += v[j] * W2[(lane + 32 * j) * NC + k];
#pragma unroll
        for (int off = 16; off > 0; off >>= 1)
            p += __shfl_xor_sync(0xFFFFFFFFu, p, off);
        h2v[k] = p;   // same value on all lanes
    }
    if (lane == 0) {
        float s2 = 0.f, d2 = 0.f;
#pragma unroll
        for (int k = 0; k < NC; k++) {
            g_h2[n * NC + k] = h2v[k];
            s2 += h2v[k] * att_src2[k];
            d2 += h2v[k] * att_dst2[k];
        }
        g_as2[n]  = s2;
        g_ad2[n]  = d2;
        g_max2[n] = NEGINF_KEY;
        g_sum2[n] = 0.f;
    }
    if (lane < NC) g_agg2[n * NC + lane] = 0.f;
}

// ---------------- layer2 edge passes ----------------
__global__ __launch_bounds__(256) void k_edge2_logit(const int* __restrict__ esrc,
                                                     const int* __restrict__ edst) {
    const int e = blockIdx.x * blockDim.x + threadIdx.x;
    if (e >= EP) return;
    int s, d;
    if (e < EE) { s = clampN(esrc[e]); d = clampN(edst[e]); }
    else        { s = d = e - EE; }
    float l = lrelu(g_as2[s] + g_ad2[d]);
    g_e2[e] = l;
    atomicMax(&g_max2[d], fkey(l));
}

__global__ __launch_bounds__(256) void k_edge2_exp(const int* __restrict__ edst) {
    const int e = blockIdx.x * blockDim.x + threadIdx.x;
    if (e >= EP) return;
    const int d = (e < EE) ? clampN(edst[e]) : (e - EE);
    float ex = expf(g_e2[e] - funkey(g_max2[d]));
    g_e2[e] = ex;
    atomicAdd(&g_sum2[d], ex);
}

__global__ __launch_bounds__(256) void k_edge2_agg(const int* __restrict__ esrc,
                                                   const int* __restrict__ edst) {
    const int e = blockIdx.x * blockDim.x + threadIdx.x;
    if (e >= EP) return;
    int s, d;
    if (e < EE) { s = clampN(esrc[e]); d = clampN(edst[e]); }
    else        { s = d = e - EE; }
    const float alpha = g_e2[e] / g_sum2[d];
    const float* hs = g_h2 + s * NC;
#pragma unroll
    for (int k = 0; k < NC; k++)
        atomicAdd(&g_agg2[d * NC + k], alpha * hs[k]);
}

// ---------------- final: out = agg2 + b2 ----------------
__global__ __launch_bounds__(256) void k_final(const float* __restrict__ b2,
                                               float* __restrict__ out) {
    const int idx = blockIdx.x * blockDim.x + threadIdx.x;
    if (idx >= NN * NC) return;
    out[idx] = g_agg2[idx] + b2[idx % NC];
}

// ---------------- launcher ----------------
extern "C" void kernel_launch(void* const* d_in, const int* in_sizes, int n_in,
                              void* d_out, int out_size) {
    const float* x        = (const float*)d_in[0];
    const int*   ei       = (const int*)d_in[1];   // JAX default: int32 (x64 disabled)
    const float* W1       = (const float*)d_in[2];
    const float* att_src1 = (const float*)d_in[3];
    const float* att_dst1 = (const float*)d_in[4];
    const float* b1       = (const float*)d_in[5];
    const float* W2       = (const float*)d_in[6];
    const float* att_src2 = (const float*)d_in[7];
    const float* att_dst2 = (const float*)d_in[8];
    const float* b2       = (const float*)d_in[9];
    float*       out      = (float*)d_out;

    const int* esrc = ei;
    const int* edst = ei + EE;

    // layer 1
    {
        dim3 grid(HC / BN, (NN + BM - 1) / BM);
        k_gemm1<<<grid, 256>>>(x, W1);
    }
    k_asad1<<<(NN * H1 + 255) / 256, 256>>>(att_src1, att_dst1);
    k_zero1<<<(NN * HC / 4 + 255) / 256, 256>>>();
    k_edge1_logit<<<(EP + 255) / 256, 256>>>(esrc, edst);
    k_edge1_exp<<<(EP + 255) / 256, 256>>>(edst);
    k_edge1_agg<<<(EP * 32 + 255) / 256, 256>>>(esrc, edst);

    // fused bias+elu+gemm2+attn precompute
    k_node2<<<(NN * 32 + 255) / 256, 256>>>(b1, W2, att_src2, att_dst2);

    // layer 2
    k_edge2_logit<<<(EP + 255) / 256, 256>>>(esrc, edst);
    k_edge2_exp<<<(EP + 255) / 256, 256>>>(edst);
    k_edge2_agg<<<(EP + 255) / 256, 256>>>(esrc, edst);
    k_final<<<(NN * NC + 255) / 256, 256>>>(b2, out);
}

// round 4
// speedup vs baseline: 1.3977x; 1.3977x over previous
#include <cuda_runtime.h>
#include <math.h>

// Problem constants (fixed by setup_inputs)
#define NN   50000
#define EE   800000
#define EP   850000      // EE + NN self loops
#define FIN  128
#define H1   4
#define HID  64
#define HC   256         // H1*HID
#define NC   10
#define NEG_SLOPE 0.2f

// ---------------- scratch (device globals; no runtime allocation) ----------
static __device__ __align__(16) float g_h1[(size_t)NN * HC];   // 51.2 MB
static __device__ __align__(16) float g_as1[NN * H1];
static __device__ __align__(16) float g_ad1[NN * H1];
static __device__ __align__(16) float g_h2[NN * NC];
static __device__ __align__(16) float g_as2[NN];
static __device__ __align__(16) float g_ad2[NN];
// CSR (dst-sorted adjacency; rebuilt every call)
static __device__ int g_deg[NN];
static __device__ int g_off[NN + 1];
static __device__ int g_pos[NN];
static __device__ int g_adj[EP];     // source node per CSR slot

// ---------------- helpers ----------------
__device__ __forceinline__ float lrelu(float x) {
    return (x > 0.f) ? x : NEG_SLOPE * x;
}
__device__ __forceinline__ int clampN(int v) {
    return v < 0 ? 0 : (v >= NN ? NN - 1 : v);
}

// ---------------- GEMM1: h1 = x @ W1  [NN,128]x[128,256], 128x128x8 -------
__global__ __launch_bounds__(256) void k_gemm1(const float* __restrict__ X,
                                               const float* __restrict__ W) {
    __shared__ float As[8][132];
    __shared__ float Bs[8][128];
    const int t  = threadIdx.x;
    const int m0 = blockIdx.y * 128;
    const int n0 = blockIdx.x * 128;
    const int ty = t >> 4;         // 0..15 -> rows ty*8..
    const int tx = t & 15;         // 0..15 -> cols tx*8..
    const int ar  = t >> 1;        // 0..127 A row
    const int akq = t & 1;         // k-quad
    const int bk  = t >> 5;        // 0..7 B k-row
    const int bc4 = t & 31;        // B col quad

    float acc[8][8];
#pragma unroll
    for (int i = 0; i < 8; i++)
#pragma unroll
        for (int j = 0; j < 8; j++) acc[i][j] = 0.f;

    for (int k0 = 0; k0 < FIN; k0 += 8) {
        const int gr = m0 + ar;
        float4 a4 = make_float4(0.f, 0.f, 0.f, 0.f);
        if (gr < NN)
            a4 = *(const float4*)(X + (size_t)gr * FIN + k0 + akq * 4);
        As[akq * 4 + 0][ar] = a4.x;
        As[akq * 4 + 1][ar] = a4.y;
        As[akq * 4 + 2][ar] = a4.z;
        As[akq * 4 + 3][ar] = a4.w;

        float4 b4 = *(const float4*)(W + (size_t)(k0 + bk) * HC + n0 + bc4 * 4);
        *(float4*)&Bs[bk][bc4 * 4] = b4;
        __syncthreads();

#pragma unroll
        for (int k = 0; k < 8; k++) {
            float a[8], b[8];
            *(float4*)&a[0] = *(const float4*)&As[k][ty * 8];
            *(float4*)&a[4] = *(const float4*)&As[k][ty * 8 + 4];
            *(float4*)&b[0] = *(const float4*)&Bs[k][tx * 8];
            *(float4*)&b[4] = *(const float4*)&Bs[k][tx * 8 + 4];
#pragma unroll
            for (int i = 0; i < 8; i++)
#pragma unroll
                for (int j = 0; j < 8; j++) acc[i][j] += a[i] * b[j];
        }
        __syncthreads();
    }
#pragma unroll
    for (int i = 0; i < 8; i++) {
        const int gr = m0 + ty * 8 + i;
        if (gr < NN) {
            float* dst = g_h1 + (size_t)gr * HC + n0 + tx * 8;
            *(float4*)dst       = make_float4(acc[i][0], acc[i][1], acc[i][2], acc[i][3]);
            *(float4*)(dst + 4) = make_float4(acc[i][4], acc[i][5], acc[i][6], acc[i][7]);
        }
    }
}

// ---------------- a_src1/a_dst1 ----------------
__global__ __launch_bounds__(256) void k_asad1(const float* __restrict__ att_src,
                                               const float* __restrict__ att_dst) {
    const int idx = blockIdx.x * blockDim.x + threadIdx.x;
    if (idx >= NN * H1) return;
    const int n = idx >> 2;
    const int h = idx & 3;
    const float* hp  = g_h1 + (size_t)n * HC + h * HID;
    const float* asp = att_src + h * HID;
    const float* adp = att_dst + h * HID;
    float ss = 0.f, sd = 0.f;
#pragma unroll
    for (int c4 = 0; c4 < HID / 4; c4++) {
        float4 v = *(const float4*)(hp + c4 * 4);
        float4 a = *(const float4*)(asp + c4 * 4);
        float4 d = *(const float4*)(adp + c4 * 4);
        ss += v.x * a.x + v.y * a.y + v.z * a.z + v.w * a.w;
        sd += v.x * d.x + v.y * d.y + v.z * d.z + v.w * d.w;
    }
    g_as1[idx] = ss;
    g_ad1[idx] = sd;
}

// ---------------- CSR build ----------------
__global__ __launch_bounds__(256) void k_zero_deg() {
    const int i = blockIdx.x * blockDim.x + threadIdx.x;
    if (i < NN) g_deg[i] = 0;
}

__global__ __launch_bounds__(256) void k_hist(const int* __restrict__ edst) {
    const int e = blockIdx.x * blockDim.x + threadIdx.x;
    if (e >= EP) return;
    const int d = (e < EE) ? clampN(edst[e]) : (e - EE);
    atomicAdd(&g_deg[d], 1);
}

__global__ __launch_bounds__(1024) void k_scan() {
    __shared__ int ws[32];
    __shared__ int s_carry;
    const int tid  = threadIdx.x;
    const int lane = tid & 31;
    const int wid  = tid >> 5;
    if (tid == 0) s_carry = 0;
    __syncthreads();
    for (int base = 0; base < NN; base += 1024) {
        const int idx = base + tid;
        const int v = (idx < NN) ? g_deg[idx] : 0;
        int x = v;
#pragma unroll
        for (int o = 1; o < 32; o <<= 1) {
            int y = __shfl_up_sync(0xFFFFFFFFu, x, o);
            if (lane >= o) x += y;
        }
        if (lane == 31) ws[wid] = x;
        __syncthreads();
        if (wid == 0) {
            int tsum = ws[lane];
#pragma unroll
            for (int o = 1; o < 32; o <<= 1) {
                int y = __shfl_up_sync(0xFFFFFFFFu, tsum, o);
                if (lane >= o) tsum += y;
            }
            ws[lane] = tsum;
        }
        __syncthreads();
        const int inc   = x + (wid ? ws[wid - 1] : 0);
        const int carry = s_carry;
        if (idx < NN) {
            const int excl = carry + inc - v;
            g_off[idx] = excl;
            g_pos[idx] = excl;
        }
        __syncthreads();
        if (tid == 1023) s_carry = carry + ws[31];
        __syncthreads();
    }
    if (tid == 0) g_off[NN] = s_carry;
}

__global__ __launch_bounds__(256) void k_fill(const int* __restrict__ esrc,
                                              const int* __restrict__ edst) {
    const int e = blockIdx.x * blockDim.x + threadIdx.x;
    if (e >= EP) return;
    int s, d;
    if (e < EE) { s = clampN(esrc[e]); d = clampN(edst[e]); }
    else        { s = d = e - EE; }
    const int p = atomicAdd(&g_pos[d], 1);
    g_adj[p] = s;
}

// ------- layer1: warp-per-dst softmax + aggregation, fused with node2 -----
__global__ __launch_bounds__(256) void k_l1(const float* __restrict__ b1,
                                            const float* __restrict__ W2,
                                            const float* __restrict__ att_src2,
                                            const float* __restrict__ att_dst2) {
    __shared__ int    sh_s[8][32];
    __shared__ float4 sh_e[8][32];
    const int warp = threadIdx.x >> 5;
    const int lane = threadIdx.x & 31;
    const int n    = blockIdx.x * 8 + warp;
    if (n >= NN) return;

    const int off = g_off[n];
    const int deg = g_off[n + 1] - off;
    const float4 ad = *(const float4*)(g_ad1 + n * 4);

    // pass 1: per-head max over neighbors
    float4 mx = make_float4(-1e30f, -1e30f, -1e30f, -1e30f);
    for (int i = lane; i < deg; i += 32) {
        const int s = g_adj[off + i];
        const float4 as = *(const float4*)(g_as1 + s * 4);
        mx.x = fmaxf(mx.x, lrelu(as.x + ad.x));
        mx.y = fmaxf(mx.y, lrelu(as.y + ad.y));
        mx.z = fmaxf(mx.z, lrelu(as.z + ad.z));
        mx.w = fmaxf(mx.w, lrelu(as.w + ad.w));
    }
#pragma unroll
    for (int o = 16; o > 0; o >>= 1) {
        mx.x = fmaxf(mx.x, __shfl_xor_sync(0xFFFFFFFFu, mx.x, o));
        mx.y = fmaxf(mx.y, __shfl_xor_sync(0xFFFFFFFFu, mx.y, o));
        mx.z = fmaxf(mx.z, __shfl_xor_sync(0xFFFFFFFFu, mx.z, o));
        mx.w = fmaxf(mx.w, __shfl_xor_sync(0xFFFFFFFFu, mx.w, o));
    }

    // pass 2: chunked exp + unnormalized aggregate
    float4 sum4 = make_float4(0.f, 0.f, 0.f, 0.f);
    float acc[8];
#pragma unroll
    for (int j = 0; j < 8; j++) acc[j] = 0.f;

    for (int base = 0; base < deg; base += 32) {
        const int cnt = min(32, deg - base);
        if (lane < cnt) {
            const int s = g_adj[off + base + lane];
            const float4 as = *(const float4*)(g_as1 + s * 4);
            float4 e4;
            e4.x = expf(lrelu(as.x + ad.x) - mx.x);
            e4.y = expf(lrelu(as.y + ad.y) - mx.y);
            e4.z = expf(lrelu(as.z + ad.z) - mx.z);
            e4.w = expf(lrelu(as.w + ad.w) - mx.w);
            sum4.x += e4.x; sum4.y += e4.y; sum4.z += e4.z; sum4.w += e4.w;
            sh_s[warp][lane] = s;
            sh_e[warp][lane] = e4;
        }
        __syncwarp();
        for (int i = 0; i < cnt; i++) {
            const int    s  = sh_s[warp][i];
            const float4 e4 = sh_e[warp][i];
            const float* hs = g_h1 + (size_t)s * HC;
            const float ev[4] = {e4.x, e4.y, e4.z, e4.w};
#pragma unroll
            for (int j = 0; j < 8; j++)
                acc[j] += ev[j >> 1] * hs[j * 32 + lane];
        }
        __syncwarp();
    }
#pragma unroll
    for (int o = 16; o > 0; o >>= 1) {
        sum4.x += __shfl_xor_sync(0xFFFFFFFFu, sum4.x, o);
        sum4.y += __shfl_xor_sync(0xFFFFFFFFu, sum4.y, o);
        sum4.z += __shfl_xor_sync(0xFFFFFFFFu, sum4.z, o);
        sum4.w += __shfl_xor_sync(0xFFFFFFFFu, sum4.w, o);
    }
    const float inv[4] = {1.f / sum4.x, 1.f / sum4.y, 1.f / sum4.z, 1.f / sum4.w};

    // fused node2: bias + ELU, GEMM2 (256->10), att2 dots
    float v[8];
#pragma unroll
    for (int j = 0; j < 8; j++) {
        const float x = acc[j] * inv[j >> 1] + b1[j * 32 + lane];
        v[j] = (x > 0.f) ? x : expm1f(x);
    }
    float h2v[NC];
#pragma unroll
    for (int k = 0; k < NC; k++) {
        float p = 0.f;
#pragma unroll
        for (int j = 0; j < 8; j++)
            p += v[j] * W2[(j * 32 + lane) * NC + k];
#pragma unroll
        for (int o = 16; o > 0; o >>= 1)
            p += __shfl_xor_sync(0xFFFFFFFFu, p, o);
        h2v[k] = p;
    }
    if (lane == 0) {
        float s2 = 0.f, d2 = 0.f;
#pragma unroll
        for (int k = 0; k < NC; k++) {
            g_h2[n * NC + k] = h2v[k];
            s2 += h2v[k] * att_src2[k];
            d2 += h2v[k] * att_dst2[k];
        }
        g_as2[n] = s2;
        g_ad2[n] = d2;
    }
}

// ------- layer2: warp-per-dst softmax + aggregation, writes out -----------
__global__ __launch_bounds__(256) void k_l2(const float* __restrict__ b2,
                                            float* __restrict__ out) {
    const int warp = threadIdx.x >> 5;
    const int lane = threadIdx.x & 31;
    const int n    = blockIdx.x * 8 + warp;
    if (n >= NN) return;

    const int off = g_off[n];
    const int deg = g_off[n + 1] - off;
    const float adv = g_ad2[n];

    float mx = -1e30f;
    for (int i = lane; i < deg; i += 32)
        mx = fmaxf(mx, lrelu(g_as2[g_adj[off + i]] + adv));
#pragma unroll
    for (int o = 16; o > 0; o >>= 1)
        mx = fmaxf(mx, __shfl_xor_sync(0xFFFFFFFFu, mx, o));

    float sum = 0.f;
    float acc[NC];
#pragma unroll
    for (int k = 0; k < NC; k++) acc[k] = 0.f;

    for (int i = lane; i < deg; i += 32) {
        const int s = g_adj[off + i];
        const float e = expf(lrelu(g_as2[s] + adv) - mx);
        sum += e;
        const float* hs = g_h2 + s * NC;
#pragma unroll
        for (int k = 0; k < NC; k++) acc[k] += e * hs[k];
    }
#pragma unroll
    for (int o = 16; o > 0; o >>= 1) {
        sum += __shfl_xor_sync(0xFFFFFFFFu, sum, o);
#pragma unroll
        for (int k = 0; k < NC; k++)
            acc[k] += __shfl_xor_sync(0xFFFFFFFFu, acc[k], o);
    }
    if (lane == 0) {
        const float invs = 1.f / sum;
#pragma unroll
        for (int k = 0; k < NC; k++)
            out[n * NC + k] = acc[k] * invs + b2[k];
    }
}

// ---------------- launcher ----------------
extern "C" void kernel_launch(void* const* d_in, const int* in_sizes, int n_in,
                              void* d_out, int out_size) {
    const float* x        = (const float*)d_in[0];
    const int*   ei       = (const int*)d_in[1];   // int32 (JAX x64 disabled)
    const float* W1       = (const float*)d_in[2];
    const float* att_src1 = (const float*)d_in[3];
    const float* att_dst1 = (const float*)d_in[4];
    const float* b1       = (const float*)d_in[5];
    const float* W2       = (const float*)d_in[6];
    const float* att_src2 = (const float*)d_in[7];
    const float* att_dst2 = (const float*)d_in[8];
    const float* b2       = (const float*)d_in[9];
    float*       out      = (float*)d_out;

    const int* esrc = ei;
    const int* edst = ei + EE;

    // CSR build (independent of gemm; same stream keeps ordering simple)
    k_zero_deg<<<(NN + 255) / 256, 256>>>();
    k_hist<<<(EP + 255) / 256, 256>>>(edst);

    // GEMM1 + attention precompute
    {
        dim3 grid(HC / 128, (NN + 127) / 128);
        k_gemm1<<<grid, 256>>>(x, W1);
    }
    k_scan<<<1, 1024>>>();
    k_fill<<<(EP + 255) / 256, 256>>>(esrc, edst);
    k_asad1<<<(NN * H1 + 255) / 256, 256>>>(att_src1, att_dst1);

    // layer1 (softmax+agg+node2 fused)
    k_l1<<<(NN + 7) / 8, 256>>>(b1, W2, att_src2, att_dst2);

    // layer2 (softmax+agg+bias fused, writes out)
    k_l2<<<(NN + 7) / 8, 256>>>(b2, out);
}

// round 5
// speedup vs baseline: 1.7426x; 1.2468x over previous
#include <cuda_runtime.h>
#include <math.h>

// Problem constants (fixed by setup_inputs)
#define NN   50000
#define EE   800000
#define EP   850000      // EE + NN self loops
#define FIN  128
#define H1   4
#define HID  64
#define HC   256         // H1*HID
#define NC   10
#define NEG_SLOPE 0.2f
#define SCAN_B 512
#define NBLK  ((NN + SCAN_B - 1) / SCAN_B)   // 98

// ---------------- scratch (device globals; no runtime allocation) ----------
static __device__ __align__(16) float g_h1[(size_t)NN * HC];   // 51.2 MB
static __device__ __align__(16) float g_as1[NN * H1];
static __device__ __align__(16) float g_ad1[NN * H1];
static __device__ __align__(16) float g_h2[NN * NC];
static __device__ __align__(16) float g_as2[NN];
static __device__ __align__(16) float g_ad2[NN];
// CSR (dst-sorted adjacency; rebuilt every call)
static __device__ int g_deg[NN];
static __device__ int g_off[NN + 1];
static __device__ int g_pos[NN];
static __device__ int g_adj[EP];     // source node per CSR slot
static __device__ int g_bsum[NBLK];
static __device__ int g_bbase[NBLK];

// ---------------- helpers ----------------
__device__ __forceinline__ float lrelu(float x) {
    return (x > 0.f) ? x : NEG_SLOPE * x;
}
__device__ __forceinline__ int clampN(int v) {
    return v < 0 ? 0 : (v >= NN ? NN - 1 : v);
}

// ---------------- GEMM1: h1 = x @ W1  [NN,128]x[128,256], 128x128x8 -------
__global__ __launch_bounds__(256) void k_gemm1(const float* __restrict__ X,
                                               const float* __restrict__ W) {
    __shared__ float As[8][132];
    __shared__ float Bs[8][128];
    const int t  = threadIdx.x;
    const int m0 = blockIdx.y * 128;
    const int n0 = blockIdx.x * 128;
    const int ty = t >> 4;         // 0..15 -> rows ty*8..
    const int tx = t & 15;         // 0..15 -> cols tx*8..
    const int ar  = t >> 1;        // 0..127 A row
    const int akq = t & 1;         // k-quad
    const int bk  = t >> 5;        // 0..7 B k-row
    const int bc4 = t & 31;        // B col quad

    float acc[8][8];
#pragma unroll
    for (int i = 0; i < 8; i++)
#pragma unroll
        for (int j = 0; j < 8; j++) acc[i][j] = 0.f;

    for (int k0 = 0; k0 < FIN; k0 += 8) {
        const int gr = m0 + ar;
        float4 a4 = make_float4(0.f, 0.f, 0.f, 0.f);
        if (gr < NN)
            a4 = *(const float4*)(X + (size_t)gr * FIN + k0 + akq * 4);
        As[akq * 4 + 0][ar] = a4.x;
        As[akq * 4 + 1][ar] = a4.y;
        As[akq * 4 + 2][ar] = a4.z;
        As[akq * 4 + 3][ar] = a4.w;

        float4 b4 = *(const float4*)(W + (size_t)(k0 + bk) * HC + n0 + bc4 * 4);
        *(float4*)&Bs[bk][bc4 * 4] = b4;
        __syncthreads();

#pragma unroll
        for (int k = 0; k < 8; k++) {
            float a[8], b[8];
            *(float4*)&a[0] = *(const float4*)&As[k][ty * 8];
            *(float4*)&a[4] = *(const float4*)&As[k][ty * 8 + 4];
            *(float4*)&b[0] = *(const float4*)&Bs[k][tx * 8];
            *(float4*)&b[4] = *(const float4*)&Bs[k][tx * 8 + 4];
#pragma unroll
            for (int i = 0; i < 8; i++)
#pragma unroll
                for (int j = 0; j < 8; j++) acc[i][j] += a[i] * b[j];
        }
        __syncthreads();
    }
#pragma unroll
    for (int i = 0; i < 8; i++) {
        const int gr = m0 + ty * 8 + i;
        if (gr < NN) {
            float* dst = g_h1 + (size_t)gr * HC + n0 + tx * 8;
            *(float4*)dst       = make_float4(acc[i][0], acc[i][1], acc[i][2], acc[i][3]);
            *(float4*)(dst + 4) = make_float4(acc[i][4], acc[i][5], acc[i][6], acc[i][7]);
        }
    }
}

// ---------------- a_src1/a_dst1 ----------------
__global__ __launch_bounds__(256) void k_asad1(const float* __restrict__ att_src,
                                               const float* __restrict__ att_dst) {
    const int idx = blockIdx.x * blockDim.x + threadIdx.x;
    if (idx >= NN * H1) return;
    const int n = idx >> 2;
    const int h = idx & 3;
    const float* hp  = g_h1 + (size_t)n * HC + h * HID;
    const float* asp = att_src + h * HID;
    const float* adp = att_dst + h * HID;
    float ss = 0.f, sd = 0.f;
#pragma unroll
    for (int c4 = 0; c4 < HID / 4; c4++) {
        float4 v = *(const float4*)(hp + c4 * 4);
        float4 a = *(const float4*)(asp + c4 * 4);
        float4 d = *(const float4*)(adp + c4 * 4);
        ss += v.x * a.x + v.y * a.y + v.z * a.z + v.w * a.w;
        sd += v.x * d.x + v.y * d.y + v.z * d.z + v.w * d.w;
    }
    g_as1[idx] = ss;
    g_ad1[idx] = sd;
}

// ---------------- CSR build ----------------
__global__ __launch_bounds__(256) void k_zero_deg() {
    const int i = blockIdx.x * blockDim.x + threadIdx.x;
    if (i < NN) g_deg[i] = 0;
}

__global__ __launch_bounds__(256) void k_hist(const int* __restrict__ edst) {
    const int e = blockIdx.x * blockDim.x + threadIdx.x;
    if (e >= EP) return;
    const int d = (e < EE) ? clampN(edst[e]) : (e - EE);
    atomicAdd(&g_deg[d], 1);
}

// scan phase A: per-block sum of degrees
__global__ __launch_bounds__(SCAN_B) void k_scanA() {
    __shared__ int ws[SCAN_B / 32];
    const int tid  = threadIdx.x;
    const int lane = tid & 31;
    const int wid  = tid >> 5;
    const int idx  = blockIdx.x * SCAN_B + tid;
    int v = (idx < NN) ? g_deg[idx] : 0;
#pragma unroll
    for (int o = 16; o > 0; o >>= 1)
        v += __shfl_xor_sync(0xFFFFFFFFu, v, o);
    if (lane == 0) ws[wid] = v;
    __syncthreads();
    if (tid < SCAN_B / 32) {
        int s = ws[tid];
#pragma unroll
        for (int o = 8; o > 0; o >>= 1)
            s += __shfl_xor_sync(0xFFFFu, s, o);
        if (tid == 0) g_bsum[blockIdx.x] = s;
    }
}

// scan phase B: exclusive scan of NBLK block sums (single small block)
__global__ __launch_bounds__(128) void k_scanB() {
    __shared__ int ws[4];
    const int tid  = threadIdx.x;
    const int lane = tid & 31;
    const int wid  = tid >> 5;
    int v = (tid < NBLK) ? g_bsum[tid] : 0;
    int x = v;
#pragma unroll
    for (int o = 1; o < 32; o <<= 1) {
        int y = __shfl_up_sync(0xFFFFFFFFu, x, o);
        if (lane >= o) x += y;
    }
    if (lane == 31) ws[wid] = x;
    __syncthreads();
    int base = 0;
    for (int w = 0; w < wid; w++) base += ws[w];
    if (tid < NBLK) g_bbase[tid] = base + x - v;   // exclusive
    if (tid == 127) g_off[NN] = base + x;          // total (= EP)
}

// scan phase C: per-block rescan + base, write off/pos
__global__ __launch_bounds__(SCAN_B) void k_scanC() {
    __shared__ int ws[SCAN_B / 32];
    const int tid  = threadIdx.x;
    const int lane = tid & 31;
    const int wid  = tid >> 5;
    const int idx  = blockIdx.x * SCAN_B + tid;
    const int v = (idx < NN) ? g_deg[idx] : 0;
    int x = v;
#pragma unroll
    for (int o = 1; o < 32; o <<= 1) {
        int y = __shfl_up_sync(0xFFFFFFFFu, x, o);
        if (lane >= o) x += y;
    }
    if (lane == 31) ws[wid] = x;
    __syncthreads();
    if (wid == 0 && lane < SCAN_B / 32) {
        int s = ws[lane];
#pragma unroll
        for (int o = 1; o < SCAN_B / 32; o <<= 1) {
            int y = __shfl_up_sync(0xFFFFu, s, o);
            if (lane >= o) s += y;
        }
        ws[lane] = s;
    }
    __syncthreads();
    if (idx < NN) {
        const int excl = g_bbase[blockIdx.x] + (wid ? ws[wid - 1] : 0) + x - v;
        g_off[idx] = excl;
        g_pos[idx] = excl;
    }
}

__global__ __launch_bounds__(256) void k_fill(const int* __restrict__ esrc,
                                              const int* __restrict__ edst) {
    const int e = blockIdx.x * blockDim.x + threadIdx.x;
    if (e >= EP) return;
    int s, d;
    if (e < EE) { s = clampN(esrc[e]); d = clampN(edst[e]); }
    else        { s = d = e - EE; }
    const int p = atomicAdd(&g_pos[d], 1);
    g_adj[p] = s;
}

// ------- layer1: warp-per-dst softmax + aggregation, fused with node2 -----
__global__ __launch_bounds__(256) void k_l1(const float* __restrict__ b1,
                                            const float* __restrict__ W2,
                                            const float* __restrict__ att_src2,
                                            const float* __restrict__ att_dst2) {
    __shared__ int    sh_s[8][32];
    __shared__ float4 sh_e[8][32];
    const int warp = threadIdx.x >> 5;
    const int lane = threadIdx.x & 31;
    const int n    = blockIdx.x * 8 + warp;
    if (n >= NN) return;

    const int off = g_off[n];
    const int deg = g_off[n + 1] - off;
    const float4 ad = *(const float4*)(g_ad1 + n * 4);

    // pass 1: per-head max over neighbors
    float4 mx = make_float4(-1e30f, -1e30f, -1e30f, -1e30f);
    for (int i = lane; i < deg; i += 32) {
        const int s = g_adj[off + i];
        const float4 as = *(const float4*)(g_as1 + s * 4);
        mx.x = fmaxf(mx.x, lrelu(as.x + ad.x));
        mx.y = fmaxf(mx.y, lrelu(as.y + ad.y));
        mx.z = fmaxf(mx.z, lrelu(as.z + ad.z));
        mx.w = fmaxf(mx.w, lrelu(as.w + ad.w));
    }
#pragma unroll
    for (int o = 16; o > 0; o >>= 1) {
        mx.x = fmaxf(mx.x, __shfl_xor_sync(0xFFFFFFFFu, mx.x, o));
        mx.y = fmaxf(mx.y, __shfl_xor_sync(0xFFFFFFFFu, mx.y, o));
        mx.z = fmaxf(mx.z, __shfl_xor_sync(0xFFFFFFFFu, mx.z, o));
        mx.w = fmaxf(mx.w, __shfl_xor_sync(0xFFFFFFFFu, mx.w, o));
    }

    // pass 2: chunked exp + unnormalized aggregate
    float4 sum4 = make_float4(0.f, 0.f, 0.f, 0.f);
    float acc[8];
#pragma unroll
    for (int j = 0; j < 8; j++) acc[j] = 0.f;

    for (int base = 0; base < deg; base += 32) {
        const int cnt = min(32, deg - base);
        if (lane < cnt) {
            const int s = g_adj[off + base + lane];
            const float4 as = *(const float4*)(g_as1 + s * 4);
            float4 e4;
            e4.x = expf(lrelu(as.x + ad.x) - mx.x);
            e4.y = expf(lrelu(as.y + ad.y) - mx.y);
            e4.z = expf(lrelu(as.z + ad.z) - mx.z);
            e4.w = expf(lrelu(as.w + ad.w) - mx.w);
            sum4.x += e4.x; sum4.y += e4.y; sum4.z += e4.z; sum4.w += e4.w;
            sh_s[warp][lane] = s;
            sh_e[warp][lane] = e4;
        }
        __syncwarp();
        for (int i = 0; i < cnt; i++) {
            const int    s  = sh_s[warp][i];
            const float4 e4 = sh_e[warp][i];
            const float* hs = g_h1 + (size_t)s * HC;
            const float ev[4] = {e4.x, e4.y, e4.z, e4.w};
#pragma unroll
            for (int j = 0; j < 8; j++)
                acc[j] += ev[j >> 1] * hs[j * 32 + lane];
        }
        __syncwarp();
    }
#pragma unroll
    for (int o = 16; o > 0; o >>= 1) {
        sum4.x += __shfl_xor_sync(0xFFFFFFFFu, sum4.x, o);
        sum4.y += __shfl_xor_sync(0xFFFFFFFFu, sum4.y, o);
        sum4.z += __shfl_xor_sync(0xFFFFFFFFu, sum4.z, o);
        sum4.w += __shfl_xor_sync(0xFFFFFFFFu, sum4.w, o);
    }
    const float inv[4] = {1.f / sum4.x, 1.f / sum4.y, 1.f / sum4.z, 1.f / sum4.w};

    // fused node2: bias + ELU, GEMM2 (256->10), att2 dots
    float v[8];
#pragma unroll
    for (int j = 0; j < 8; j++) {
        const float x = acc[j] * inv[j >> 1] + b1[j * 32 + lane];
        v[j] = (x > 0.f) ? x : expm1f(x);
    }
    float h2v[NC];
#pragma unroll
    for (int k = 0; k < NC; k++) {
        float p = 0.f;
#pragma unroll
        for (int j = 0; j < 8; j++)
            p += v[j] * W2[(j * 32 + lane) * NC + k];
#pragma unroll
        for (int o = 16; o > 0; o >>= 1)
            p += __shfl_xor_sync(0xFFFFFFFFu, p, o);
        h2v[k] = p;
    }
    if (lane == 0) {
        float s2 = 0.f, d2 = 0.f;
#pragma unroll
        for (int k = 0; k < NC; k++) {
            g_h2[n * NC + k] = h2v[k];
            s2 += h2v[k] * att_src2[k];
            d2 += h2v[k] * att_dst2[k];
        }
        g_as2[n] = s2;
        g_ad2[n] = d2;
    }
}

// ------- layer2: warp-per-dst softmax + aggregation, writes out -----------
__global__ __launch_bounds__(256) void k_l2(const float* __restrict__ b2,
                                            float* __restrict__ out) {
    const int warp = threadIdx.x >> 5;
    const int lane = threadIdx.x & 31;
    const int n    = blockIdx.x * 8 + warp;
    if (n >= NN) return;

    const int off = g_off[n];
    const int deg = g_off[n + 1] - off;
    const float adv = g_ad2[n];

    float mx = -1e30f;
    for (int i = lane; i < deg; i += 32)
        mx = fmaxf(mx, lrelu(g_as2[g_adj[off + i]] + adv));
#pragma unroll
    for (int o = 16; o > 0; o >>= 1)
        mx = fmaxf(mx, __shfl_xor_sync(0xFFFFFFFFu, mx, o));

    float sum = 0.f;
    float acc[NC];
#pragma unroll
    for (int k = 0; k < NC; k++) acc[k] = 0.f;

    for (int i = lane; i < deg; i += 32) {
        const int s = g_adj[off + i];
        const float e = expf(lrelu(g_as2[s] + adv) - mx);
        sum += e;
        const float* hs = g_h2 + s * NC;
#pragma unroll
        for (int k = 0; k < NC; k++) acc[k] += e * hs[k];
    }
#pragma unroll
    for (int o = 16; o > 0; o >>= 1) {
        sum += __shfl_xor_sync(0xFFFFFFFFu, sum, o);
#pragma unroll
        for (int k = 0; k < NC; k++)
            acc[k] += __shfl_xor_sync(0xFFFFFFFFu, acc[k], o);
    }
    if (lane == 0) {
        const float invs = 1.f / sum;
#pragma unroll
        for (int k = 0; k < NC; k++)
            out[n * NC + k] = acc[k] * invs + b2[k];
    }
}

// ---------------- launcher ----------------
extern "C" void kernel_launch(void* const* d_in, const int* in_sizes, int n_in,
                              void* d_out, int out_size) {
    const float* x        = (const float*)d_in[0];
    const int*   ei       = (const int*)d_in[1];   // int32 (JAX x64 disabled)
    const float* W1       = (const float*)d_in[2];
    const float* att_src1 = (const float*)d_in[3];
    const float* att_dst1 = (const float*)d_in[4];
    const float* b1       = (const float*)d_in[5];
    const float* W2       = (const float*)d_in[6];
    const float* att_src2 = (const float*)d_in[7];
    const float* att_dst2 = (const float*)d_in[8];
    const float* b2       = (const float*)d_in[9];
    float*       out      = (float*)d_out;

    const int* esrc = ei;
    const int* edst = ei + EE;

    // CSR build
    k_zero_deg<<<(NN + 255) / 256, 256>>>();
    k_hist<<<(EP + 255) / 256, 256>>>(edst);
    k_scanA<<<NBLK, SCAN_B>>>();
    k_scanB<<<1, 128>>>();
    k_scanC<<<NBLK, SCAN_B>>>();
    k_fill<<<(EP + 255) / 256, 256>>>(esrc, edst);

    // GEMM1 + attention precompute
    {
        dim3 grid(HC / 128, (NN + 127) / 128);
        k_gemm1<<<grid, 256>>>(x, W1);
    }
    k_asad1<<<(NN * H1 + 255) / 256, 256>>>(att_src1, att_dst1);

    // layer1 (softmax+agg+node2 fused)
    k_l1<<<(NN + 7) / 8, 256>>>(b1, W2, att_src2, att_dst2);

    // layer2 (softmax+agg+bias fused, writes out)
    k_l2<<<(NN + 7) / 8, 256>>>(b2, out);
}